// round 1
// baseline (speedup 1.0000x reference)
#include <cuda_runtime.h>
#include <cuda_bf16.h>

// FilterLayer: y[b,c,h,w] = sum_{i,j in 5x5} xpad[b,c,h+i,w+j] * f[b,i*5+j,h,w]
// x: [4,3,512,512] f32, f: [4,25,512,512] f32, out: [4,3,512,512] f32, pad=2.
//
// Strategy: HBM-bound (f stream = 105 MB dominates). One thread computes 4
// consecutive w-pixels for all 3 channels. x tile staged in shared with halo;
// per (c, tap-row) 8 consecutive floats pulled into registers (2x LDS.128),
// tap reuse resolved in registers. f read as coalesced float4 (25 LDG.128
// per thread -> high MLP).

#define Hc 512
#define Wc 512
#define Bc 4
#define WIN 5
#define PAD 2

#define TILE_W 128   // pixels per block in w (32 threads x 4 px)
#define TILE_H 8     // pixels per block in h
#define SW (TILE_W + 2*PAD)   // 132
#define SH (TILE_H + 2*PAD)   // 12

__global__ __launch_bounds__(256, 4)
void filter_kernel(const float* __restrict__ x,
                   const float* __restrict__ f,
                   float* __restrict__ out)
{
    __shared__ float sx[3][SH][SW];   // 3*12*132*4 = 19008 B

    const int tx = threadIdx.x;       // 0..31
    const int ty = threadIdx.y;       // 0..7
    const int b  = blockIdx.z;
    const int h0 = blockIdx.y * TILE_H;
    const int w0 = blockIdx.x * TILE_W;

    // ---- Stage x tile (with zero halo) into shared ----
    const int tid = ty * 32 + tx;     // 0..255
    const int total = 3 * SH * SW;    // 4752
    #pragma unroll 4
    for (int idx = tid; idx < total; idx += 256) {
        int c   = idx / (SH * SW);
        int rem = idx - c * (SH * SW);
        int r   = rem / SW;
        int col = rem - r * SW;
        int gh = h0 + r - PAD;
        int gw = w0 + col - PAD;
        float v = 0.0f;
        if ((unsigned)gh < Hc && (unsigned)gw < Wc)
            v = x[((b * 3 + c) * Hc + gh) * Wc + gw];
        sx[c][r][col] = v;
    }
    __syncthreads();

    // ---- Compute 4 pixels x 3 channels per thread ----
    const int h = h0 + ty;
    const int w = w0 + tx * 4;

    float acc[3][4];
    #pragma unroll
    for (int c = 0; c < 3; c++)
        #pragma unroll
        for (int p = 0; p < 4; p++)
            acc[c][p] = 0.0f;

    const float* fbase = f + ((long)(b * (WIN*WIN)) * Hc + h) * Wc + w;

    #pragma unroll
    for (int i = 0; i < WIN; i++) {
        // 8 consecutive x values per channel for this tap row (registers)
        float xr[3][8];
        #pragma unroll
        for (int c = 0; c < 3; c++) {
            const float4 a = *reinterpret_cast<const float4*>(&sx[c][ty + i][tx * 4]);
            const float4 bb = *reinterpret_cast<const float4*>(&sx[c][ty + i][tx * 4 + 4]);
            xr[c][0] = a.x;  xr[c][1] = a.y;  xr[c][2] = a.z;  xr[c][3] = a.w;
            xr[c][4] = bb.x; xr[c][5] = bb.y; xr[c][6] = bb.z; xr[c][7] = bb.w;
        }
        #pragma unroll
        for (int j = 0; j < WIN; j++) {
            const int k = i * WIN + j;
            const float4 fv = *reinterpret_cast<const float4*>(fbase + (long)k * (Hc * Wc));
            #pragma unroll
            for (int c = 0; c < 3; c++) {
                acc[c][0] = fmaf(xr[c][0 + j], fv.x, acc[c][0]);
                acc[c][1] = fmaf(xr[c][1 + j], fv.y, acc[c][1]);
                acc[c][2] = fmaf(xr[c][2 + j], fv.z, acc[c][2]);
                acc[c][3] = fmaf(xr[c][3 + j], fv.w, acc[c][3]);
            }
        }
    }

    // ---- Write out ----
    #pragma unroll
    for (int c = 0; c < 3; c++) {
        float4 o;
        o.x = acc[c][0]; o.y = acc[c][1]; o.z = acc[c][2]; o.w = acc[c][3];
        *reinterpret_cast<float4*>(out + ((long)(b * 3 + c) * Hc + h) * Wc + w) = o;
    }
}

extern "C" void kernel_launch(void* const* d_in, const int* in_sizes, int n_in,
                              void* d_out, int out_size)
{
    const float* x = (const float*)d_in[0];
    const float* f = (const float*)d_in[1];
    float* out = (float*)d_out;

    dim3 block(32, 8, 1);
    dim3 grid(Wc / TILE_W, Hc / TILE_H, Bc);
    filter_kernel<<<grid, block>>>(x, f, out);
}

// round 2
// speedup vs baseline: 1.1412x; 1.1412x over previous
#include <cuda_runtime.h>
#include <cuda_bf16.h>

// FilterLayer: y[b,c,h,w] = sum_{i,j in 5x5} xpad[b,c,h+i,w+j] * f[b,i*5+j,h,w]
// x: [4,3,512,512] f32, f: [4,25,512,512] f32, out: [4,3,512,512] f32, pad=2.
//
// R2: HBM-bound, latency-exposed. Changes vs R1:
//  - row-batched f loads (5x LDG.128 issued together -> MLP)
//  - per-channel x register window (8 floats live, not 24) -> fewer regs
//  - __launch_bounds__(256,5) -> 48 regs -> 5 blocks/SM (occ up)
//  - __ldcs on f (stream-once), __stcs on out -> keep L2 for x halo reuse

#define Hc 512
#define Wc 512
#define Bc 4
#define WIN 5
#define PAD 2

#define TILE_W 128   // 32 threads x 4 px
#define TILE_H 8
#define SW (TILE_W + 2*PAD)   // 132
#define SH (TILE_H + 2*PAD)   // 12

__global__ __launch_bounds__(256, 5)
void filter_kernel(const float* __restrict__ x,
                   const float* __restrict__ f,
                   float* __restrict__ out)
{
    __shared__ float sx[3][SH][SW];   // 19008 B

    const int tx = threadIdx.x;       // 0..31
    const int ty = threadIdx.y;       // 0..7
    const int b  = blockIdx.z;
    const int h0 = blockIdx.y * TILE_H;
    const int w0 = blockIdx.x * TILE_W;

    // ---- Stage x tile (with zero halo) into shared ----
    const int tid = ty * 32 + tx;
    const int total = 3 * SH * SW;    // 4752
    #pragma unroll 4
    for (int idx = tid; idx < total; idx += 256) {
        int c   = idx / (SH * SW);
        int rem = idx - c * (SH * SW);
        int r   = rem / SW;
        int col = rem - r * SW;
        int gh = h0 + r - PAD;
        int gw = w0 + col - PAD;
        float v = 0.0f;
        if ((unsigned)gh < Hc && (unsigned)gw < Wc)
            v = x[((b * 3 + c) * Hc + gh) * Wc + gw];
        sx[c][r][col] = v;
    }
    __syncthreads();

    const int h = h0 + ty;
    const int w = w0 + tx * 4;

    float acc[3][4];
    #pragma unroll
    for (int c = 0; c < 3; c++)
        #pragma unroll
        for (int p = 0; p < 4; p++)
            acc[c][p] = 0.0f;

    const float* fbase = f + ((long)(b * (WIN*WIN)) * Hc + h) * Wc + w;

    #pragma unroll
    for (int i = 0; i < WIN; i++) {
        // Batch-load this tap row's 5 filter vectors (stream-once -> .cs)
        float4 fv[WIN];
        #pragma unroll
        for (int j = 0; j < WIN; j++)
            fv[j] = __ldcs(reinterpret_cast<const float4*>(
                        fbase + (long)(i * WIN + j) * (Hc * Wc)));

        #pragma unroll
        for (int c = 0; c < 3; c++) {
            // 8 consecutive x values for this (c, tap-row)
            const float4 a  = *reinterpret_cast<const float4*>(&sx[c][ty + i][tx * 4]);
            const float4 bb = *reinterpret_cast<const float4*>(&sx[c][ty + i][tx * 4 + 4]);
            float xr[8];
            xr[0] = a.x;  xr[1] = a.y;  xr[2] = a.z;  xr[3] = a.w;
            xr[4] = bb.x; xr[5] = bb.y; xr[6] = bb.z; xr[7] = bb.w;

            #pragma unroll
            for (int j = 0; j < WIN; j++) {
                acc[c][0] = fmaf(xr[0 + j], fv[j].x, acc[c][0]);
                acc[c][1] = fmaf(xr[1 + j], fv[j].y, acc[c][1]);
                acc[c][2] = fmaf(xr[2 + j], fv[j].z, acc[c][2]);
                acc[c][3] = fmaf(xr[3 + j], fv[j].w, acc[c][3]);
            }
        }
    }

    #pragma unroll
    for (int c = 0; c < 3; c++) {
        float4 o;
        o.x = acc[c][0]; o.y = acc[c][1]; o.z = acc[c][2]; o.w = acc[c][3];
        __stcs(reinterpret_cast<float4*>(out + ((long)(b * 3 + c) * Hc + h) * Wc + w), o);
    }
}

extern "C" void kernel_launch(void* const* d_in, const int* in_sizes, int n_in,
                              void* d_out, int out_size)
{
    const float* x = (const float*)d_in[0];
    const float* f = (const float*)d_in[1];
    float* out = (float*)d_out;

    dim3 block(32, 8, 1);
    dim3 grid(Wc / TILE_W, Hc / TILE_H, Bc);
    filter_kernel<<<grid, block>>>(x, f, out);
}